// round 10
// baseline (speedup 1.0000x reference)
#include <cuda_runtime.h>
#include <math.h>
#include <stdint.h>

#define BATCH   1024
#define IN_DIM  256
#define NG      512
#define OUT_DIM 256
#define CAP     2048.0f
#define SLOTS   16

__device__ __align__(16) float g_gauss[BATCH * NG];

__device__ __forceinline__ uint32_t fbits(float f) { return __float_as_uint(f); }

__device__ __forceinline__ void mma_tf32(float d[4],
    uint32_t a0, uint32_t a1, uint32_t a2, uint32_t a3,
    uint32_t b0, uint32_t b1) {
    asm volatile(
        "mma.sync.aligned.m16n8k8.row.col.f32.tf32.tf32.f32 "
        "{%0,%1,%2,%3}, {%4,%5,%6,%7}, {%8,%9}, {%0,%1,%2,%3};\n"
        : "+f"(d[0]), "+f"(d[1]), "+f"(d[2]), "+f"(d[3])
        : "r"(a0), "r"(a1), "r"(a2), "r"(a3), "r"(b0), "r"(b1));
}

__device__ __forceinline__ void cp16(void* smem_dst, const void* gsrc) {
    uint32_t s = (uint32_t)__cvta_generic_to_shared(smem_dst);
    asm volatile("cp.async.cg.shared.global [%0], [%1], 16;\n" :: "r"(s), "l"(gsrc));
}
__device__ __forceinline__ void cp_commit() {
    asm volatile("cp.async.commit_group;\n");
}
template <int N>
__device__ __forceinline__ void cp_wait() {
    asm volatile("cp.async.wait_group %0;\n" :: "n"(N));
}

// ============================================================================
// GEMM1 (prep fused), 512 threads: warps 0-7's threads (0-255) build B1/B2/
// bias/excess-lists; threads 256-511 stage the X tile concurrently.
// Mainloop: 16 warps (4m x 4n), warp tile 16x16, no syncs, no gmem.
// ============================================================================
#define B_ST 260
#define XS_OFF 0
#define B1_OFF (64 * 256)
#define B2_OFF (B1_OFF + 64 * B_ST)
#define BS_OFF (B2_OFF + 64 * B_ST)
#define CN_OFF (BS_OFF + 64)
#define LE_OFF (CN_OFF + 64)
#define LC_OFF (LE_OFF + 64 * SLOTS)
#define LK_OFF (LC_OFF + 64 * SLOTS)
#define SMEM_FLOATS (LK_OFF + 64 * SLOTS)
#define SMEM_BYTES (SMEM_FLOATS * 4)

__global__ void __launch_bounds__(512, 1)
gemm1_kernel(const float* __restrict__ x,
             const float* __restrict__ centers,
             const float* __restrict__ stds) {
    extern __shared__ float sm[];
    float* Xs    = sm + XS_OFF;
    float* B1s   = sm + B1_OFF;
    float* B2s   = sm + B2_OFF;
    float* biasS = sm + BS_OFF;
    int*   cntS  = (int*)(sm + CN_OFF);
    float* leS   = sm + LE_OFF;
    float* lcS   = sm + LC_OFF;
    int*   lkS   = (int*)(sm + LK_OFF);

    const int tid  = threadIdx.x;
    const int lane = tid & 31;
    const int qr   = lane >> 2;
    const int ql   = lane & 3;
    const int w    = tid >> 5;            // 0..15
    const int wm   = (w >> 2) * 16;       // 0,16,32,48
    const int wn   = (w & 3) * 16;        // 0,16,32,48
    const int m0   = blockIdx.y * 64;
    const int n0   = blockIdx.x * 64;
    const int swzf = qr << 2;

    // ---- staging: threads 0-255 -> B tiles + lists; 256-511 -> X tile ----
    if (tid < 256) {
        const int lr  = tid >> 2;
        const int q   = tid & 3;
        const int lk4 = q * 4;
        float bias_part = 0.f;
        int   base      = 0;
        #pragma unroll 4
        for (int it = 0; it < 16; ++it) {
            const int k0 = it * 16 + lk4;
            float4 cv = *(const float4*)&centers[(n0 + lr) * IN_DIM + k0];
            float4 sv = *(const float4*)&stds   [(n0 + lr) * IN_DIM + k0];
            float cc[4] = {cv.x, cv.y, cv.z, cv.w};
            float inv[4];
            inv[0] = 1.f / (sv.x * sv.x); inv[1] = 1.f / (sv.y * sv.y);
            inv[2] = 1.f / (sv.z * sv.z); inv[3] = 1.f / (sv.w * sv.w);
            float ic[4];
            ic[0] = fminf(inv[0], CAP); ic[1] = fminf(inv[1], CAP);
            ic[2] = fminf(inv[2], CAP); ic[3] = fminf(inv[3], CAP);
            float4 b1v = make_float4(cc[0]*ic[0], cc[1]*ic[1], cc[2]*ic[2], cc[3]*ic[3]);
            float4 b2v = make_float4(-0.5f*ic[0], -0.5f*ic[1], -0.5f*ic[2], -0.5f*ic[3]);
            *(float4*)&B1s[lr * B_ST + k0] = b1v;
            *(float4*)&B2s[lr * B_ST + k0] = b2v;
            bias_part -= 0.5f * (cc[0]*cc[0]*ic[0] + cc[1]*cc[1]*ic[1] +
                                 cc[2]*cc[2]*ic[2] + cc[3]*cc[3]*ic[3]);

            unsigned m = (inv[0] > CAP ? 1u : 0u) | (inv[1] > CAP ? 2u : 0u) |
                         (inv[2] > CAP ? 4u : 0u) | (inv[3] > CAP ? 8u : 0u);
            int cnt = __popc(m);
            const int qb = lane & ~3;
            int c0 = __shfl_sync(0xffffffffu, cnt, qb + 0);
            int c1 = __shfl_sync(0xffffffffu, cnt, qb + 1);
            int c2 = __shfl_sync(0xffffffffu, cnt, qb + 2);
            int c3 = __shfl_sync(0xffffffffu, cnt, qb + 3);
            int prefix = (q > 0 ? c0 : 0) + (q > 1 ? c1 : 0) + (q > 2 ? c2 : 0);
            int slot = base + prefix;
            #pragma unroll
            for (int b = 0; b < 4; ++b) {
                if ((m >> b) & 1u) {
                    if (slot < SLOTS) {
                        leS[lr * SLOTS + slot] = -0.5f * (inv[b] - CAP);
                        lcS[lr * SLOTS + slot] = cc[b];
                        lkS[lr * SLOTS + slot] = k0 + b;
                    }
                    slot++;
                }
            }
            base += c0 + c1 + c2 + c3;
        }
        bias_part += __shfl_xor_sync(0xffffffffu, bias_part, 1);
        bias_part += __shfl_xor_sync(0xffffffffu, bias_part, 2);
        if (q == 0) {
            biasS[lr] = bias_part;
            cntS[lr]  = base < SLOTS ? base : SLOTS;
        }
    } else {
        const int xt   = tid - 256;
        const int lr   = xt >> 2;
        const int lk4  = (xt & 3) * 4;
        const int swzl = (lr & 7) << 2;
        #pragma unroll 4
        for (int it = 0; it < 16; ++it) {
            const int k0 = it * 16 + lk4;
            float4 v = *(const float4*)&x[(m0 + lr) * IN_DIM + k0];
            *(float4*)&Xs[lr * 256 + (k0 ^ swzl)] = v;
        }
    }
    __syncthreads();   // the ONLY barrier

    // ---- mainloop: 16 warps, warp tile 16x16, pure LDS + HMMA ----
    float acc[2][4] = {};

    #pragma unroll 2
    for (int it = 0; it < 16; ++it) {
        #pragma unroll
        for (int ks = 0; ks < 16; ks += 8) {
            const int kb  = it * 16 + ks;
            const int kc0 = (kb + ql)     ^ swzf;
            const int kc1 = (kb + ql + 4) ^ swzf;
            const int r0  = (wm + qr) * 256;
            float f0 = Xs[r0 + kc0];
            float f1 = Xs[r0 + 2048 + kc0];
            float f2 = Xs[r0 + kc1];
            float f3 = Xs[r0 + 2048 + kc1];
            uint32_t a0 = fbits(f0),      a1 = fbits(f1);
            uint32_t a2 = fbits(f2),      a3 = fbits(f3);
            uint32_t s0 = fbits(f0 * f0), s1 = fbits(f1 * f1);
            uint32_t s2 = fbits(f2 * f2), s3 = fbits(f3 * f3);
            #pragma unroll
            for (int nt = 0; nt < 2; ++nt) {
                const int nb = (wn + nt * 8 + qr) * B_ST + kb;
                uint32_t b10 = fbits(B1s[nb + ql]);
                uint32_t b11 = fbits(B1s[nb + ql + 4]);
                uint32_t b20 = fbits(B2s[nb + ql]);
                uint32_t b21 = fbits(B2s[nb + ql + 4]);
                mma_tf32(acc[nt], a0, a1, a2, a3, b10, b11);
                mma_tf32(acc[nt], s0, s1, s2, s3, b20, b21);
            }
        }
    }

    // ---- sparse excess correction (exact fp32, direct form) ----
    float corr[4][2];
    #pragma unroll
    for (int gi = 0; gi < 4; ++gi) {
        const int g   = wn + (gi >> 1) * 8 + 2 * ql + (gi & 1);
        const int cnt = cntS[g];
        float c0 = 0.f, c1 = 0.f;
        for (int j = 0; j < cnt; ++j) {
            float e  = leS[g * SLOTS + j];
            float cc = lcS[g * SLOTS + j];
            int   kx = lkS[g * SLOTS + j] ^ swzf;
            float d0 = Xs[(wm     + qr) * 256 + kx] - cc;
            float d1 = Xs[(wm + 8 + qr) * 256 + kx] - cc;
            c0 += e * d0 * d0; c1 += e * d1 * d1;
        }
        corr[gi][0] = c0; corr[gi][1] = c1;
    }

    // ---- epilogue ----
    const int mrow = m0 + wm + qr;
    #pragma unroll
    for (int nt = 0; nt < 2; ++nt) {
        const int ncol = wn + nt * 8 + 2 * ql;
        const float b0 = biasS[ncol], b1 = biasS[ncol + 1];
        const int g0 = nt * 2, g1 = nt * 2 + 1;
        float2 e0, e1;
        e0.x = __expf(acc[nt][0] + b0 + corr[g0][0]);
        e0.y = __expf(acc[nt][1] + b1 + corr[g1][0]);
        e1.x = __expf(acc[nt][2] + b0 + corr[g0][1]);
        e1.y = __expf(acc[nt][3] + b1 + corr[g1][1]);
        *(float2*)&g_gauss[ mrow      * NG + n0 + ncol] = e0;
        *(float2*)&g_gauss[(mrow + 8) * NG + n0 + ncol] = e1;
    }
}

// ============================================================================
// GEMM2, 512 threads: full-K smem residency (A 64x512 @516, B 512x32 @40),
// 4 K-chunk cp.async groups issued up front, one barrier per chunk.
// 16 warps (4m x 4n), warp tile 16x8.
// ============================================================================
#define G2A_ST 516
#define G2B_ST 40
#define G2A_OFF 0
#define G2B_OFF (64 * G2A_ST)
#define G2_SMEM_FLOATS (G2B_OFF + 512 * G2B_ST)
#define G2_SMEM_BYTES (G2_SMEM_FLOATS * 4)

__global__ void __launch_bounds__(512, 1)
gemm2_kernel(const float* __restrict__ W, float* __restrict__ out) {
    extern __shared__ float sm2[];
    float* As = sm2 + G2A_OFF;   // [64][G2A_ST]
    float* Bs = sm2 + G2B_OFF;   // [512][G2B_ST]

    const int tid  = threadIdx.x;
    const int lane = tid & 31;
    const int qr   = lane >> 2;
    const int ql   = lane & 3;
    const int w    = tid >> 5;            // 0..15
    const int wm   = (w >> 2) * 16;       // 0,16,32,48
    const int wn   = (w & 3) * 8;         // 0,8,16,24
    const int m0   = blockIdx.y * 64;
    const int n0   = blockIdx.x * 32;

    // ---- issue ALL loads as 4 K-chunk groups (chunk = 128 k) ----
    #pragma unroll
    for (int kc = 0; kc < 4; ++kc) {
        #pragma unroll
        for (int i = 0; i < 4; ++i) {        // A: 2048 float4 chunks
            const int idx = tid + i * 512;
            const int row = idx >> 5;
            const int c4  = (idx & 31) * 4;
            cp16(&As[row * G2A_ST + kc * 128 + c4],
                 &g_gauss[(m0 + row) * NG + kc * 128 + c4]);
        }
        #pragma unroll
        for (int i = 0; i < 2; ++i) {        // B: 1024 float4 chunks
            const int idx  = tid + i * 512;
            const int krow = idx >> 3;
            const int n4   = (idx & 7) * 4;
            cp16(&Bs[(kc * 128 + krow) * G2B_ST + n4],
                 &W[(kc * 128 + krow) * OUT_DIM + n0 + n4]);
        }
        cp_commit();
    }

    float acc[4] = {};

    auto compute_chunk = [&](int kc) {
        const int kb = kc * 128;
        #pragma unroll
        for (int ks = 0; ks < 128; ks += 8) {
            const int ar = (wm + qr) * G2A_ST + kb + ks;
            uint32_t a0 = fbits(As[ar + ql]);
            uint32_t a1 = fbits(As[ar + 8 * G2A_ST + ql]);
            uint32_t a2 = fbits(As[ar + ql + 4]);
            uint32_t a3 = fbits(As[ar + 8 * G2A_ST + ql + 4]);
            uint32_t b0 = fbits(Bs[(kb + ks + ql    ) * G2B_ST + wn + qr]);
            uint32_t b1 = fbits(Bs[(kb + ks + ql + 4) * G2B_ST + wn + qr]);
            mma_tf32(acc, a0, a1, a2, a3, b0, b1);
        }
    };

    cp_wait<3>(); __syncthreads(); compute_chunk(0);
    cp_wait<2>(); __syncthreads(); compute_chunk(1);
    cp_wait<1>(); __syncthreads(); compute_chunk(2);
    cp_wait<0>(); __syncthreads(); compute_chunk(3);

    const int mrow = m0 + wm + qr;
    const int ncol = n0 + wn + 2 * ql;
    *(float2*)&out[ mrow      * OUT_DIM + ncol] = make_float2(acc[0], acc[1]);
    *(float2*)&out[(mrow + 8) * OUT_DIM + ncol] = make_float2(acc[2], acc[3]);
}

extern "C" void kernel_launch(void* const* d_in, const int* in_sizes, int n_in,
                              void* d_out, int out_size) {
    const float* x       = (const float*)d_in[0];
    const float* centers = (const float*)d_in[1];
    const float* stds    = (const float*)d_in[2];
    const float* weights = (const float*)d_in[3];
    float* out = (float*)d_out;

    static int configured = 0;
    if (!configured) {
        cudaFuncSetAttribute(gemm1_kernel,
                             cudaFuncAttributeMaxDynamicSharedMemorySize, SMEM_BYTES);
        cudaFuncSetAttribute(gemm2_kernel,
                             cudaFuncAttributeMaxDynamicSharedMemorySize, G2_SMEM_BYTES);
        configured = 1;
    }

    gemm1_kernel<<<dim3(NG / 64, BATCH / 64), 512, SMEM_BYTES>>>(x, centers, stds);
    gemm2_kernel<<<dim3(OUT_DIM / 32, BATCH / 64), 512, G2_SMEM_BYTES>>>(weights, out);
}

// round 11
// speedup vs baseline: 1.0928x; 1.0928x over previous
#include <cuda_runtime.h>
#include <math.h>
#include <stdint.h>

#define BATCH   1024
#define IN_DIM  256
#define NG      512
#define OUT_DIM 256
#define CAP     2048.0f
#define SLOTS   16

__device__ __align__(16) float g_gauss[BATCH * NG];
__device__ int g_arrive[16];
__device__ int g_depart[16];

__device__ __forceinline__ uint32_t fbits(float f) { return __float_as_uint(f); }

__device__ __forceinline__ void mma_tf32(float d[4],
    uint32_t a0, uint32_t a1, uint32_t a2, uint32_t a3,
    uint32_t b0, uint32_t b1) {
    asm volatile(
        "mma.sync.aligned.m16n8k8.row.col.f32.tf32.tf32.f32 "
        "{%0,%1,%2,%3}, {%4,%5,%6,%7}, {%8,%9}, {%0,%1,%2,%3};\n"
        : "+f"(d[0]), "+f"(d[1]), "+f"(d[2]), "+f"(d[3])
        : "r"(a0), "r"(a1), "r"(a2), "r"(a3), "r"(b0), "r"(b1));
}

__device__ __forceinline__ void cp16(void* smem_dst, const void* gsrc) {
    uint32_t s = (uint32_t)__cvta_generic_to_shared(smem_dst);
    asm volatile("cp.async.cg.shared.global [%0], [%1], 16;\n" :: "r"(s), "l"(gsrc));
}
__device__ __forceinline__ void cp_commit() {
    asm volatile("cp.async.commit_group;\n");
}
template <int N>
__device__ __forceinline__ void cp_wait() {
    asm volatile("cp.async.wait_group %0;\n" :: "n"(N));
}

// ---- union smem layout (floats) ----
// phase 1
#define B_ST 260
#define XS_OFF 0                          // 16384
#define B1_OFF 16384                      // 16640
#define B2_OFF 33024                      // 16640
#define BS_OFF 49664                      // 64
#define CN_OFF 49728                      // 64
#define LE_OFF 49792                      // 1024
#define LC_OFF 50816                      // 1024
#define LK_OFF 51840                      // 1024  -> phase1 end 52864
// phase 2 (valid only after barrier)
#define G2A_ST 516
#define G2B_ST 40
#define A2_OFF 0                          // 64*516 = 33024
#define B2S_OFF 33024                     // 512*40 = 20480 -> end 53504
#define SMEM_FLOATS 53504
#define SMEM_BYTES (SMEM_FLOATS * 4)      // 214016 B

__global__ void __launch_bounds__(256, 1)
fused_kernel(const float* __restrict__ x,
             const float* __restrict__ centers,
             const float* __restrict__ stds,
             const float* __restrict__ W,
             float* __restrict__ out) {
    extern __shared__ float sm[];
    const int tid  = threadIdx.x;
    const int lane = tid & 31;
    const int qr   = lane >> 2;
    const int ql   = lane & 3;
    const int w    = tid >> 5;
    const int gy   = blockIdx.y;

    // ========================= PHASE 1: fused-prep Gaussian GEMM ============
    {
        float* Xs    = sm + XS_OFF;
        float* B1s   = sm + B1_OFF;
        float* B2s   = sm + B2_OFF;
        float* biasS = sm + BS_OFF;
        int*   cntS  = (int*)(sm + CN_OFF);
        float* leS   = sm + LE_OFF;
        float* lcS   = sm + LC_OFF;
        int*   lkS   = (int*)(sm + LK_OFF);

        const int wm   = (w >> 2) * 32;
        const int wn   = (w & 3) * 16;
        const int m0   = gy * 64;
        const int n0   = blockIdx.x * 64;
        const int lr   = tid >> 2;
        const int q    = tid & 3;
        const int lk4  = q * 4;
        const int swzl = (lr & 7) << 2;
        const int swzf = qr << 2;

        float bias_part = 0.f;
        int   base      = 0;
        #pragma unroll 4
        for (int it = 0; it < 16; ++it) {
            const int k0 = it * 16 + lk4;
            float4 xv = *(const float4*)&x[(m0 + lr) * IN_DIM + k0];
            *(float4*)&Xs[lr * 256 + (k0 ^ swzl)] = xv;

            float4 cv = *(const float4*)&centers[(n0 + lr) * IN_DIM + k0];
            float4 sv = *(const float4*)&stds   [(n0 + lr) * IN_DIM + k0];
            float cc[4] = {cv.x, cv.y, cv.z, cv.w};
            float inv[4];
            inv[0] = 1.f / (sv.x * sv.x); inv[1] = 1.f / (sv.y * sv.y);
            inv[2] = 1.f / (sv.z * sv.z); inv[3] = 1.f / (sv.w * sv.w);
            float ic[4];
            ic[0] = fminf(inv[0], CAP); ic[1] = fminf(inv[1], CAP);
            ic[2] = fminf(inv[2], CAP); ic[3] = fminf(inv[3], CAP);
            float4 b1v = make_float4(cc[0]*ic[0], cc[1]*ic[1], cc[2]*ic[2], cc[3]*ic[3]);
            float4 b2v = make_float4(-0.5f*ic[0], -0.5f*ic[1], -0.5f*ic[2], -0.5f*ic[3]);
            *(float4*)&B1s[lr * B_ST + k0] = b1v;
            *(float4*)&B2s[lr * B_ST + k0] = b2v;
            bias_part -= 0.5f * (cc[0]*cc[0]*ic[0] + cc[1]*cc[1]*ic[1] +
                                 cc[2]*cc[2]*ic[2] + cc[3]*cc[3]*ic[3]);

            unsigned m = (inv[0] > CAP ? 1u : 0u) | (inv[1] > CAP ? 2u : 0u) |
                         (inv[2] > CAP ? 4u : 0u) | (inv[3] > CAP ? 8u : 0u);
            int cnt = __popc(m);
            const int qb = lane & ~3;
            int c0 = __shfl_sync(0xffffffffu, cnt, qb + 0);
            int c1 = __shfl_sync(0xffffffffu, cnt, qb + 1);
            int c2 = __shfl_sync(0xffffffffu, cnt, qb + 2);
            int c3 = __shfl_sync(0xffffffffu, cnt, qb + 3);
            int prefix = (q > 0 ? c0 : 0) + (q > 1 ? c1 : 0) + (q > 2 ? c2 : 0);
            int slot = base + prefix;
            #pragma unroll
            for (int b = 0; b < 4; ++b) {
                if ((m >> b) & 1u) {
                    if (slot < SLOTS) {
                        leS[lr * SLOTS + slot] = -0.5f * (inv[b] - CAP);
                        lcS[lr * SLOTS + slot] = cc[b];
                        lkS[lr * SLOTS + slot] = k0 + b;
                    }
                    slot++;
                }
            }
            base += c0 + c1 + c2 + c3;
        }
        bias_part += __shfl_xor_sync(0xffffffffu, bias_part, 1);
        bias_part += __shfl_xor_sync(0xffffffffu, bias_part, 2);
        if (q == 0) {
            biasS[lr] = bias_part;
            cntS[lr]  = base < SLOTS ? base : SLOTS;
        }
        __syncthreads();

        float acc[2][2][4];
        #pragma unroll
        for (int a = 0; a < 2; a++)
            #pragma unroll
            for (int b = 0; b < 2; b++)
                #pragma unroll
                for (int c = 0; c < 4; c++) acc[a][b][c] = 0.f;

        #pragma unroll 2
        for (int it = 0; it < 16; ++it) {
            #pragma unroll
            for (int ks = 0; ks < 16; ks += 8) {
                const int kb  = it * 16 + ks;
                const int kc0 = (kb + ql)     ^ swzf;
                const int kc1 = (kb + ql + 4) ^ swzf;
                uint32_t ax[2][4], aq[2][4];
                #pragma unroll
                for (int mt = 0; mt < 2; ++mt) {
                    const int r0 = (wm + mt * 16 + qr) * 256;
                    float f0 = Xs[r0 + kc0];
                    float f1 = Xs[r0 + 2048 + kc0];
                    float f2 = Xs[r0 + kc1];
                    float f3 = Xs[r0 + 2048 + kc1];
                    ax[mt][0] = fbits(f0);      ax[mt][1] = fbits(f1);
                    ax[mt][2] = fbits(f2);      ax[mt][3] = fbits(f3);
                    aq[mt][0] = fbits(f0 * f0); aq[mt][1] = fbits(f1 * f1);
                    aq[mt][2] = fbits(f2 * f2); aq[mt][3] = fbits(f3 * f3);
                }
                #pragma unroll
                for (int nt = 0; nt < 2; ++nt) {
                    const int nb = (wn + nt * 8 + qr) * B_ST + kb;
                    uint32_t b10 = fbits(B1s[nb + ql]);
                    uint32_t b11 = fbits(B1s[nb + ql + 4]);
                    uint32_t b20 = fbits(B2s[nb + ql]);
                    uint32_t b21 = fbits(B2s[nb + ql + 4]);
                    #pragma unroll
                    for (int mt = 0; mt < 2; ++mt) {
                        mma_tf32(acc[mt][nt], ax[mt][0], ax[mt][1], ax[mt][2], ax[mt][3], b10, b11);
                        mma_tf32(acc[mt][nt], aq[mt][0], aq[mt][1], aq[mt][2], aq[mt][3], b20, b21);
                    }
                }
            }
        }

        float corr[4][4];
        #pragma unroll
        for (int gi = 0; gi < 4; ++gi) {
            const int g   = wn + (gi >> 1) * 8 + 2 * ql + (gi & 1);
            const int cnt = cntS[g];
            float c0 = 0.f, c1 = 0.f, c2 = 0.f, c3 = 0.f;
            for (int j = 0; j < cnt; ++j) {
                float e  = leS[g * SLOTS + j];
                float cc = lcS[g * SLOTS + j];
                int   kx = lkS[g * SLOTS + j] ^ swzf;
                float d0 = Xs[(wm      + qr) * 256 + kx] - cc;
                float d1 = Xs[(wm +  8 + qr) * 256 + kx] - cc;
                float d2 = Xs[(wm + 16 + qr) * 256 + kx] - cc;
                float d3 = Xs[(wm + 24 + qr) * 256 + kx] - cc;
                c0 += e * d0 * d0; c1 += e * d1 * d1;
                c2 += e * d2 * d2; c3 += e * d3 * d3;
            }
            corr[gi][0] = c0; corr[gi][1] = c1; corr[gi][2] = c2; corr[gi][3] = c3;
        }

        #pragma unroll
        for (int mt = 0; mt < 2; ++mt) {
            const int mrow = m0 + wm + mt * 16 + qr;
            #pragma unroll
            for (int nt = 0; nt < 2; ++nt) {
                const int ncol = wn + nt * 8 + 2 * ql;
                const float b0 = biasS[ncol], b1 = biasS[ncol + 1];
                const int g0 = nt * 2, g1 = nt * 2 + 1;
                float2 e0, e1;
                e0.x = __expf(acc[mt][nt][0] + b0 + corr[g0][mt * 2]);
                e0.y = __expf(acc[mt][nt][1] + b1 + corr[g1][mt * 2]);
                e1.x = __expf(acc[mt][nt][2] + b0 + corr[g0][mt * 2 + 1]);
                e1.y = __expf(acc[mt][nt][3] + b1 + corr[g1][mt * 2 + 1]);
                *(float2*)&g_gauss[ mrow      * NG + n0 + ncol] = e0;
                *(float2*)&g_gauss[(mrow + 8) * NG + n0 + ncol] = e1;
            }
        }
    }

    // ================ per-row-group barrier (8 CTAs share rows gy*64..+63) ==
    __threadfence();        // each thread: its g_gauss stores visible GPU-wide
    __syncthreads();        // all threads fenced before the arrival
    if (tid == 0) {
        atomicAdd(&g_arrive[gy], 1);
        while (((volatile int*)g_arrive)[gy] < 8) { }
    }
    __syncthreads();        // all threads see phase-1 done; smem reusable
    __threadfence();

    // ========================= PHASE 2: out = gauss . W =====================
    {
        float* As = sm + A2_OFF;    // [64][G2A_ST]
        float* Bs = sm + B2S_OFF;   // [512][G2B_ST]

        const int wm = (w >> 1) * 16;   // 0,16,32,48
        const int wn = (w & 1) * 16;    // 0,16
        const int m0 = gy * 64;
        const int n0 = blockIdx.x * 32;

        #pragma unroll
        for (int kc = 0; kc < 4; ++kc) {
            #pragma unroll
            for (int i = 0; i < 8; ++i) {
                const int idx = tid + i * 256;
                const int row = idx >> 5;
                const int c4  = (idx & 31) * 4;
                cp16(&As[row * G2A_ST + kc * 128 + c4],
                     &g_gauss[(m0 + row) * NG + kc * 128 + c4]);
            }
            #pragma unroll
            for (int i = 0; i < 4; ++i) {
                const int idx  = tid + i * 256;
                const int krow = idx >> 3;
                const int n4   = (idx & 7) * 4;
                cp16(&Bs[(kc * 128 + krow) * G2B_ST + n4],
                     &W[(kc * 128 + krow) * OUT_DIM + n0 + n4]);
            }
            cp_commit();
        }

        float acc[2][4] = {};

        auto compute_chunk = [&](int kc) {
            const int kb = kc * 128;
            #pragma unroll
            for (int ks = 0; ks < 128; ks += 8) {
                const int ar = (wm + qr) * G2A_ST + kb + ks;
                uint32_t a0 = fbits(As[ar + ql]);
                uint32_t a1 = fbits(As[ar + 8 * G2A_ST + ql]);
                uint32_t a2 = fbits(As[ar + ql + 4]);
                uint32_t a3 = fbits(As[ar + 8 * G2A_ST + ql + 4]);
                #pragma unroll
                for (int nt = 0; nt < 2; ++nt) {
                    const int nb = wn + nt * 8;
                    uint32_t b0 = fbits(Bs[(kb + ks + ql    ) * G2B_ST + nb + qr]);
                    uint32_t b1 = fbits(Bs[(kb + ks + ql + 4) * G2B_ST + nb + qr]);
                    mma_tf32(acc[nt], a0, a1, a2, a3, b0, b1);
                }
            }
        };

        cp_wait<3>(); __syncthreads(); compute_chunk(0);
        cp_wait<2>(); __syncthreads(); compute_chunk(1);
        cp_wait<1>(); __syncthreads(); compute_chunk(2);
        cp_wait<0>(); __syncthreads(); compute_chunk(3);

        const int mrow = m0 + wm + qr;
        #pragma unroll
        for (int nt = 0; nt < 2; ++nt) {
            const int ncol = n0 + wn + nt * 8 + 2 * ql;
            *(float2*)&out[ mrow      * OUT_DIM + ncol] = make_float2(acc[nt][0], acc[nt][1]);
            *(float2*)&out[(mrow + 8) * OUT_DIM + ncol] = make_float2(acc[nt][2], acc[nt][3]);
        }
    }

    // ---- reset counters for next (graph-replayed) launch ----
    if (tid == 0) {
        int d = atomicAdd(&g_depart[gy], 1);
        if (d == 7) {                 // last CTA of group: everyone passed spin
            atomicExch(&g_arrive[gy], 0);
            atomicExch(&g_depart[gy], 0);
        }
    }
}

extern "C" void kernel_launch(void* const* d_in, const int* in_sizes, int n_in,
                              void* d_out, int out_size) {
    const float* x       = (const float*)d_in[0];
    const float* centers = (const float*)d_in[1];
    const float* stds    = (const float*)d_in[2];
    const float* weights = (const float*)d_in[3];
    float* out = (float*)d_out;

    static int configured = 0;
    if (!configured) {
        cudaFuncSetAttribute(fused_kernel,
                             cudaFuncAttributeMaxDynamicSharedMemorySize, SMEM_BYTES);
        configured = 1;
    }

    fused_kernel<<<dim3(8, 16), 256, SMEM_BYTES>>>(x, centers, stds, weights, out);
}